// round 1
// baseline (speedup 1.0000x reference)
#include <cuda_runtime.h>

#define NQ 8
#define DIM 256
#define BATCH 32768
#define NW 26

// One warp per sample. Lane L holds amplitudes i = L*8 + k (k=0..7).
// PennyLane wire w <-> index bit (7-w). Wires 0..4 are cross-lane (shfl),
// wires 5..7 are in-register. State is exactly real throughout.
__global__ __launch_bounds__(256) void qae_kernel(const float* __restrict__ x,
                                                  const float* __restrict__ w,
                                                  float* __restrict__ out) {
    __shared__ float sc[NW], ss[NW];
    int tid = threadIdx.x;
    if (tid < NW) {
        float s, c;
        sincosf(0.5f * w[tid], &s, &c);
        sc[tid] = c; ss[tid] = s;
    }
    __syncthreads();

    int warp = (blockIdx.x * blockDim.x + tid) >> 5;   // sample id
    int lane = tid & 31;

    const float4* xp = reinterpret_cast<const float4*>(x + (size_t)warp * DIM + lane * 8);
    float4 v0 = xp[0], v1 = xp[1];
    float r[8] = {v0.x, v0.y, v0.z, v0.w, v1.x, v1.y, v1.z, v1.w};

    // squared norm of the raw input (normalization folded into epilogue)
    float n2 = 0.f;
    #pragma unroll
    for (int k = 0; k < 8; k++) n2 = fmaf(r[k], r[k], n2);
    #pragma unroll
    for (int m = 16; m; m >>= 1) n2 += __shfl_xor_sync(0xffffffffu, n2, m);

    // CZ layer parity mask: pairs (0,1), (0,j),(1,j) for j=2..7.
    // parity(i) = (b0&b1) ^ ((b0^b1) & popc(rest)&1), b0=bit7, b1=bit6
    unsigned czm = 0;
    #pragma unroll
    for (int k = 0; k < 8; k++) {
        int i = (lane << 3) | k;
        int b0 = (i >> 7) & 1, b1 = (i >> 6) & 1;
        int rp = __popc(i & 63) & 1;
        int par = (b0 & b1) ^ ((b0 ^ b1) & rp);
        czm |= (unsigned)par << k;
    }

    // ---- circuit: 3 full layers ----
    #pragma unroll
    for (int l = 0; l < 3; l++) {
        // wires 0..4: cross-lane rotations, lane mask = 16 >> q
        #pragma unroll
        for (int q = 0; q < 5; q++) {
            float c = sc[l * 8 + q], s = ss[l * 8 + q];
            int lm = 16 >> q;
            float se = (lane & lm) ? s : -s;
            #pragma unroll
            for (int k = 0; k < 8; k++) {
                float p = __shfl_xor_sync(0xffffffffu, r[k], lm);
                r[k] = fmaf(se, p, c * r[k]);
            }
        }
        // wire 5: pairs (k, k+4)
        {
            float c = sc[l * 8 + 5], s = ss[l * 8 + 5];
            #pragma unroll
            for (int k = 0; k < 4; k++) {
                float a = r[k], b = r[k + 4];
                r[k]     = fmaf(c, a, -s * b);
                r[k + 4] = fmaf(s, a,  c * b);
            }
        }
        // wire 6: pairs (k, k+2) within each group of 4
        {
            float c = sc[l * 8 + 6], s = ss[l * 8 + 6];
            #pragma unroll
            for (int g = 0; g < 8; g += 4)
                #pragma unroll
                for (int k = 0; k < 2; k++) {
                    float a = r[g + k], b = r[g + k + 2];
                    r[g + k]     = fmaf(c, a, -s * b);
                    r[g + k + 2] = fmaf(s, a,  c * b);
                }
        }
        // wire 7: pairs (k, k+1)
        {
            float c = sc[l * 8 + 7], s = ss[l * 8 + 7];
            #pragma unroll
            for (int k = 0; k < 8; k += 2) {
                float a = r[k], b = r[k + 1];
                r[k]     = fmaf(c, a, -s * b);
                r[k + 1] = fmaf(s, a,  c * b);
            }
        }
        // fused CZ layer: flip fp32 sign bit where parity set (SHL + LOP3)
        #pragma unroll
        for (int k = 0; k < 8; k++) {
            unsigned sb = (czm << (31 - k)) & 0x80000000u;
            r[k] = __uint_as_float(__float_as_uint(r[k]) ^ sb);
        }
    }

    // final layer: RY on trash wires 0,1 (weights 24,25)
    #pragma unroll
    for (int q = 0; q < 2; q++) {
        float c = sc[24 + q], s = ss[24 + q];
        int lm = 16 >> q;
        float se = (lane & lm) ? s : -s;
        #pragma unroll
        for (int k = 0; k < 8; k++) {
            float p = __shfl_xor_sync(0xffffffffu, r[k], lm);
            r[k] = fmaf(se, p, c * r[k]);
        }
    }

    // ---- expectations (wire6 -> bit1 of k, wire7 -> bit0 of k; all in-register) ----
    float x6 = 0, z6 = 0, x7 = 0, z7 = 0, xx = 0, yy = 0, zz = 0;
    #pragma unroll
    for (int k = 0; k < 8; k++) {
        int b0 = k & 1, b1 = (k >> 1) & 1;
        float v = r[k];
        x6 = fmaf(v, r[k ^ 2], x6);
        x7 = fmaf(v, r[k ^ 1], x7);
        float p3 = v * r[k ^ 3];
        xx += p3;
        yy += (b0 ^ b1) ? p3 : -p3;          // Y(x)Y factor: -1 iff bits equal
        float sq = v * v;
        z6 += b1 ? -sq : sq;
        z7 += b0 ? -sq : sq;
        zz += (b0 ^ b1) ? -sq : sq;
    }
    #pragma unroll
    for (int m = 16; m; m >>= 1) {
        x6 += __shfl_xor_sync(0xffffffffu, x6, m);
        z6 += __shfl_xor_sync(0xffffffffu, z6, m);
        x7 += __shfl_xor_sync(0xffffffffu, x7, m);
        z7 += __shfl_xor_sync(0xffffffffu, z7, m);
        xx += __shfl_xor_sync(0xffffffffu, xx, m);
        yy += __shfl_xor_sync(0xffffffffu, yy, m);
        zz += __shfl_xor_sync(0xffffffffu, zz, m);
    }
    if (lane == 0) {
        float inv = 1.0f / n2;
        float* o = out + (size_t)warp * 9;
        o[0] = x6 * inv;
        o[1] = 0.0f;            // <Y> on real state is exactly 0
        o[2] = z6 * inv;
        o[3] = x7 * inv;
        o[4] = 0.0f;
        o[5] = z7 * inv;
        o[6] = xx * inv;
        o[7] = yy * inv;
        o[8] = zz * inv;
    }
}

extern "C" void kernel_launch(void* const* d_in, const int* in_sizes, int n_in,
                              void* d_out, int out_size) {
    // metadata order: x [32768*256], weights [26] — guard against swap by size
    const float* x = (const float*)d_in[0];
    const float* w = (const float*)d_in[1];
    if (n_in >= 2 && in_sizes[0] == NW) { const float* t = x; x = w; w = t; }
    float* out = (float*)d_out;
    qae_kernel<<<BATCH / 8, 256>>>(x, w, out);
}